// round 17
// baseline (speedup 1.0000x reference)
#include <cuda_runtime.h>
#include <cuda_fp16.h>
#include <cstdint>

// Problem constants (fixed by the reference)
#define NUM_USERS 50000
#define NUM_ITEMS 50000
#define N_NODES   (NUM_USERS + NUM_ITEMS)   // 100000
#define EMB_DIM   64
#define N_LAYERS  3
#define NNZ_MAX   3200000

// Scratch buffers (__device__ globals: allocation-guard safe)
// Propagation buffers in fp16: row = 64 halves = 128 B = 8 x uint4
__device__ __half2 g_bufX[(size_t)N_NODES * (EMB_DIM / 2)];
__device__ __half2 g_bufY[(size_t)N_NODES * (EMB_DIM / 2)];
__device__ float   g_acc [(size_t)N_NODES * EMB_DIM];       // fp32 accumulator
__device__ int     g_ptr [N_NODES + 1];
__device__ int     g_pos [N_NODES];
__device__ int2    g_edges[NNZ_MAX];   // .x = src, .y = bitcast(val)

// ---------------------------------------------------------------------------
// zero destination-degree counters
// ---------------------------------------------------------------------------
__global__ void zero_pos_kernel(int* __restrict__ pos)
{
    for (int i = blockIdx.x * blockDim.x + threadIdx.x; i < N_NODES;
         i += gridDim.x * blockDim.x)
        pos[i] = 0;
}

// ---------------------------------------------------------------------------
// histogram of edge destinations
// ---------------------------------------------------------------------------
__global__ void hist_kernel(const int* __restrict__ edge_dst,
                            int* __restrict__ pos, int nnz)
{
    for (int e = blockIdx.x * blockDim.x + threadIdx.x; e < nnz;
         e += gridDim.x * blockDim.x)
        atomicAdd(&pos[edge_dst[e]], 1);
}

// ---------------------------------------------------------------------------
// single-block exclusive scan: counts (in g_pos) -> g_ptr; reset g_pos = ptr
// ---------------------------------------------------------------------------
__global__ void scan_kernel(int* __restrict__ pos, int* __restrict__ ptr)
{
    const int T = 1024;
    const int tid = threadIdx.x;
    const int chunk = (N_NODES + T - 1) / T;   // 98
    int start = tid * chunk;
    int end = start + chunk; if (end > N_NODES) end = N_NODES;

    int sum = 0;
    for (int i = start; i < end && start < N_NODES; ++i) sum += pos[i];

    __shared__ int sh[T];
    sh[tid] = sum;
    __syncthreads();
    for (int d = 1; d < T; d <<= 1) {
        int v = (tid >= d) ? sh[tid - d] : 0;
        __syncthreads();
        sh[tid] += v;
        __syncthreads();
    }
    int run = sh[tid] - sum;   // exclusive prefix of this chunk

    if (start < N_NODES) {
        for (int i = start; i < end; ++i) {
            int c = pos[i];
            ptr[i] = run;
            pos[i] = run;      // cursor copy for bucket scatter
            run += c;
        }
        if (end == N_NODES) ptr[N_NODES] = run;
    }
}

// ---------------------------------------------------------------------------
// bucket scatter: edges -> dst-sorted (src, val) pairs
// ---------------------------------------------------------------------------
__global__ void bucket_kernel(const float* __restrict__ edge_val,
                              const int*   __restrict__ edge_src,
                              const int*   __restrict__ edge_dst,
                              int* __restrict__ pos,
                              int2* __restrict__ edges, int nnz)
{
    for (int e = blockIdx.x * blockDim.x + threadIdx.x; e < nnz;
         e += gridDim.x * blockDim.x) {
        int p = atomicAdd(&pos[edge_dst[e]], 1);
        edges[p] = make_int2(edge_src[e], __float_as_int(edge_val[e]));
    }
}

// ---------------------------------------------------------------------------
// init: X = fp16(concat(user_emb, item_emb)); acc = fp32 concat
// ---------------------------------------------------------------------------
__global__ void init_kernel(const float4* __restrict__ user_emb,
                            const float4* __restrict__ item_emb,
                            __half2* __restrict__ X,
                            float4* __restrict__ acc)
{
    const int n4 = N_NODES * EMB_DIM / 4;
    const int user4 = NUM_USERS * EMB_DIM / 4;
    for (int i = blockIdx.x * blockDim.x + threadIdx.x; i < n4;
         i += gridDim.x * blockDim.x) {
        float4 v = (i < user4) ? user_emb[i] : item_emb[i - user4];
        acc[i] = v;
        X[2 * i]     = __float22half2_rn(make_float2(v.x, v.y));
        X[2 * i + 1] = __float22half2_rn(make_float2(v.z, v.w));
    }
}

// ---------------------------------------------------------------------------
// accumulate 8 halves (one uint4 = 4 x half2) scaled by v into s[8]
// ---------------------------------------------------------------------------
__device__ __forceinline__ void accum8(float* __restrict__ s, uint4 m, float v)
{
    float2 f;
    f = __half22float2(*reinterpret_cast<__half2*>(&m.x)); s[0] += v * f.x; s[1] += v * f.y;
    f = __half22float2(*reinterpret_cast<__half2*>(&m.y)); s[2] += v * f.x; s[3] += v * f.y;
    f = __half22float2(*reinterpret_cast<__half2*>(&m.z)); s[4] += v * f.x; s[5] += v * f.y;
    f = __half22float2(*reinterpret_cast<__half2*>(&m.w)); s[6] += v * f.x; s[7] += v * f.y;
}

// ---------------------------------------------------------------------------
// pull layer: out[n] = sum_{e in bucket(n)} val_e * cur[src_e]
// 4 nodes per warp: 8-lane group per node, lane owns 8 dims (one uint4, 16B).
// Edge chunking: each lane loads its own edge (coalesced 64B per group),
// then 8 shuffle-broadcast iterations issue 8 independent gathers (MLP=8).
// Tail edges padded with val=0 inside the chunk (no divergent remainder).
// fp32 accumulation; fuses acc += out; writes fp16 nxt when needed.
// ---------------------------------------------------------------------------
__global__ void pull_kernel(const uint4* __restrict__ cur,   // 8 uint4 per node row
                            uint4* __restrict__ nxt,
                            float4* __restrict__ acc,        // 16 float4 per node
                            const int*  __restrict__ ptr,
                            const int2* __restrict__ edges,
                            int write_nxt)
{
    const int warp = blockIdx.x * (blockDim.x >> 5) + (threadIdx.x >> 5);
    const int lane = threadIdx.x & 31;
    const int grp  = lane >> 3;        // 0..3 : node within warp
    const int sub  = lane & 7;         // 0..7 : 16B slot within row
    const int n = warp * 4 + grp;
    if (n >= N_NODES) return;

    const int beg = ptr[n];
    const int end = ptr[n + 1];

    float s[8] = {0.f, 0.f, 0.f, 0.f, 0.f, 0.f, 0.f, 0.f};

    for (int base = beg; base < end; base += 8) {
        // each lane stages one edge of this group's 8-edge chunk (coalesced)
        const int idx = base + sub;
        int2 e = (idx < end) ? edges[idx] : make_int2(0, 0);  // val=0 pad

        #pragma unroll
        for (int j = 0; j < 8; ++j) {
            const int srcLane = (grp << 3) | j;
            const int   es = __shfl_sync(0xffffffffu, e.x, srcLane);
            const float ev = __int_as_float(__shfl_sync(0xffffffffu, e.y, srcLane));
            const uint4 m = cur[(size_t)es * 8 + sub];   // 8 independent gathers
            accum8(s, m, ev);
        }
    }

    // lane sub owns dims [8*sub, 8*sub+8)
    if (write_nxt) {
        uint4 p;
        __half2 h;
        h = __float22half2_rn(make_float2(s[0], s[1])); p.x = *reinterpret_cast<unsigned*>(&h);
        h = __float22half2_rn(make_float2(s[2], s[3])); p.y = *reinterpret_cast<unsigned*>(&h);
        h = __float22half2_rn(make_float2(s[4], s[5])); p.z = *reinterpret_cast<unsigned*>(&h);
        h = __float22half2_rn(make_float2(s[6], s[7])); p.w = *reinterpret_cast<unsigned*>(&h);
        nxt[(size_t)n * 8 + sub] = p;
    }

    const size_t o = (size_t)n * 16 + 2 * sub;
    float4 a0 = acc[o];
    float4 a1 = acc[o + 1];
    a0.x += s[0]; a0.y += s[1]; a0.z += s[2]; a0.w += s[3];
    a1.x += s[4]; a1.y += s[5]; a1.z += s[6]; a1.w += s[7];
    acc[o]     = a0;
    acc[o + 1] = a1;
}

// ---------------------------------------------------------------------------
// gamma[b] = (1/16) * dot(acc[users[b]], acc[NUM_USERS + items[b]])
// ---------------------------------------------------------------------------
__global__ void gamma_kernel(const float* __restrict__ acc,
                             const int* __restrict__ users,
                             const int* __restrict__ items,
                             float* __restrict__ out,
                             int batch)
{
    int b = blockIdx.x * (blockDim.x >> 5) + (threadIdx.x >> 5);
    if (b >= batch) return;
    const int lane = threadIdx.x & 31;

    const int u = users[b];
    const int it = items[b];

    const float2 a = reinterpret_cast<const float2*>(acc + (size_t)u * EMB_DIM)[lane];
    const float2 c = reinterpret_cast<const float2*>(
        acc + (size_t)(NUM_USERS + it) * EMB_DIM)[lane];

    float s = a.x * c.x + a.y * c.y;
    #pragma unroll
    for (int o = 16; o > 0; o >>= 1) s += __shfl_xor_sync(0xffffffffu, s, o);

    if (lane == 0) out[b] = s * (1.0f / 16.0f);  // (1/(L+1))^2 = 1/16
}

// ---------------------------------------------------------------------------
// launch
// ---------------------------------------------------------------------------
extern "C" void kernel_launch(void* const* d_in, const int* in_sizes, int n_in,
                              void* d_out, int out_size)
{
    const float* user_emb = (const float*)d_in[0];
    const float* item_emb = (const float*)d_in[1];
    const float* edge_val = (const float*)d_in[2];
    const int*   edge_src = (const int*)  d_in[3];
    const int*   edge_dst = (const int*)  d_in[4];
    const int*   users    = (const int*)  d_in[5];
    const int*   items    = (const int*)  d_in[6];
    const int nnz   = in_sizes[2];
    const int batch = in_sizes[5];
    float* out = (float*)d_out;

    __half2 *X, *Y;
    float *acc;
    int *ptr, *pos;
    int2 *edges;
    cudaGetSymbolAddress((void**)&X,     g_bufX);
    cudaGetSymbolAddress((void**)&Y,     g_bufY);
    cudaGetSymbolAddress((void**)&acc,   g_acc);
    cudaGetSymbolAddress((void**)&ptr,   g_ptr);
    cudaGetSymbolAddress((void**)&pos,   g_pos);
    cudaGetSymbolAddress((void**)&edges, g_edges);

    const int TB = 256;

    // ---- build dst-sorted CSR ----
    zero_pos_kernel<<<(N_NODES + TB - 1) / TB, TB>>>(pos);
    hist_kernel<<<(nnz + TB - 1) / TB, TB>>>(edge_dst, pos, nnz);
    scan_kernel<<<1, 1024>>>(pos, ptr);
    bucket_kernel<<<(nnz + TB - 1) / TB, TB>>>(edge_val, edge_src, edge_dst,
                                               pos, edges, nnz);

    // ---- init embeddings + accumulator ----
    const int n4 = N_NODES * EMB_DIM / 4;
    init_kernel<<<(n4 + TB - 1) / TB, TB>>>((const float4*)user_emb,
                                            (const float4*)item_emb,
                                            X, (float4*)acc);

    // ---- 3 pull layers (4 nodes per warp, 8 lanes per node) ----
    const int warps_per_block = TB / 32;                  // 8
    const int nodes_per_block = 4 * warps_per_block;      // 32
    const int node_blocks = (N_NODES + nodes_per_block - 1) / nodes_per_block;

    // Layer 1: X -> Y, acc += Y
    pull_kernel<<<node_blocks, TB>>>((const uint4*)X, (uint4*)Y, (float4*)acc,
                                     ptr, edges, 1);
    // Layer 2: Y -> X, acc += X
    pull_kernel<<<node_blocks, TB>>>((const uint4*)Y, (uint4*)X, (float4*)acc,
                                     ptr, edges, 1);
    // Layer 3: X -> (discard), acc += out only
    pull_kernel<<<node_blocks, TB>>>((const uint4*)X, (uint4*)Y, (float4*)acc,
                                     ptr, edges, 0);

    // ---- scoring ----
    const int gamma_blocks = (batch + warps_per_block - 1) / warps_per_block;
    gamma_kernel<<<gamma_blocks, TB>>>(acc, users, items, out, batch);
}